// round 13
// baseline (speedup 1.0000x reference)
#include <cuda_runtime.h>

#define N_ATOMS 10000
#define N_PAIRS 500000
#define N_DESC  64

#define TABLE_TPB 256
#define TABLE_BLOCKS ((N_ATOMS * N_DESC / 4 + TABLE_TPB - 1) / TABLE_TPB)   // 625

// Precomputed per-atom table: g[n,d] = (1 - tanh^2(coeffs*w1+b1)) * w1[d] * w_last[d]
__device__ float g_table[N_ATOMS * N_DESC];
// Per-block energy partials from the table kernel
__device__ float e_partials[TABLE_BLOCKS];

// ---------------------------------------------------------------------------
// Kernel 1: build g table (float4-vectorized), zero forces, write per-block
// energy partials. One thread per 4 (atom,descriptor) elements.
// ---------------------------------------------------------------------------
__global__ void table_energy_kernel(const float4* __restrict__ coeffs4,
                                    const float4* __restrict__ w1_4,
                                    const float4* __restrict__ b1_4,
                                    const float4* __restrict__ wl_4,
                                    float* __restrict__ out_f) {   // out+1
    int idx = blockIdx.x * blockDim.x + threadIdx.x;   // over 160000 float4s
    float e_contrib = 0.0f;
    if (idx < N_ATOMS * N_DESC / 4) {
        int d4 = idx & (N_DESC / 4 - 1);               // descriptor group 0..15
        float4 w  = w1_4[d4];
        float4 b  = b1_4[d4];
        float4 wl = wl_4[d4];
        float4 c  = coeffs4[idx];
        float ex = tanhf(fmaf(c.x, w.x, b.x));
        float ey = tanhf(fmaf(c.y, w.y, b.y));
        float ez = tanhf(fmaf(c.z, w.z, b.z));
        float ew = tanhf(fmaf(c.w, w.w, b.w));
        float4 g;
        g.x = (1.0f - ex * ex) * w.x * wl.x;
        g.y = (1.0f - ey * ey) * w.y * wl.y;
        g.z = (1.0f - ez * ez) * w.z * wl.z;
        g.w = (1.0f - ew * ew) * w.w * wl.w;
        *(float4*)(g_table + idx * 4) = g;
        e_contrib = fmaf(ex, wl.x, fmaf(ey, wl.y, fmaf(ez, wl.z, ew * wl.w)));
    }
    // zero the force output (3*N_ATOMS = 30000 floats; out_f only 4B-aligned)
    if (idx < 3 * N_ATOMS) out_f[idx] = 0.0f;

    // block reduction of energy contribution
    __shared__ float red[TABLE_TPB / 32];
    #pragma unroll
    for (int o = 16; o > 0; o >>= 1)
        e_contrib += __shfl_xor_sync(0xFFFFFFFFu, e_contrib, o);
    int lane = threadIdx.x & 31;
    int wid = threadIdx.x >> 5;
    if (lane == 0) red[wid] = e_contrib;
    __syncthreads();
    if (wid == 0) {
        float v = (lane < (TABLE_TPB >> 5)) ? red[lane] : 0.0f;
        #pragma unroll
        for (int o = 16; o > 0; o >>= 1)
            v += __shfl_xor_sync(0xFFFFFFFFu, v, o);
        if (lane == 0) e_partials[blockIdx.x] = v;
    }
}

// ---------------------------------------------------------------------------
// Kernel 2: pair contraction + scatter. Non-persistent (wall-clock best):
// TWO pairs per warp, lanes 0-15 -> pair 2w, lanes 16-31 -> pair 2w+1.
// Each lane owns 4 descriptors (float4); each deriv load is one warp-wide
// contiguous 512 B LDG.128. Derivs use __ldcs (evict-first) so L2 keeps
// g_table + the force accumulator resident.
// Block 0 / warp 0 additionally finalizes the energy from the partials.
// Grid covers exactly N_PAIRS/2 warps — no bounds check needed.
// ---------------------------------------------------------------------------
__global__ void __launch_bounds__(256) pair_kernel(
    const float* __restrict__ derivs,          // [3, N_PAIRS, 64]
    const int* __restrict__ central,
    const int* __restrict__ neigh,
    const float* __restrict__ b_last,
    float* __restrict__ out)                   // [0]=energy, [1..]=forces [3,N_ATOMS]
{
    const unsigned lane = threadIdx.x & 31;
    float* out_f = out + 1;

    // ---- energy finalize (one warp; table kernel already completed) ----
    if (blockIdx.x == 0 && (threadIdx.x >> 5) == 0) {
        float v = 0.0f;
        for (int i = lane; i < TABLE_BLOCKS; i += 32) v += e_partials[i];
        #pragma unroll
        for (int o = 16; o > 0; o >>= 1)
            v += __shfl_xor_sync(0xFFFFFFFFu, v, o);
        if (lane == 0) out[0] = v * (1.0f / (float)N_ATOMS) + b_last[0];
    }

    unsigned gtid = blockIdx.x * 256 + threadIdx.x;
    unsigned warp = gtid >> 5;
    unsigned p = warp * 2 + (lane >> 4);       // pair served by this lane
    unsigned l16 = lane & 15;

    int c  = __ldg(central + p);
    int nb = __ldg(neigh + p);

    // gather g row (L2-resident), 4 descriptors per lane
    float4 g = *(const float4*)(g_table + (size_t)c * N_DESC + l16 * 4);

    const float* base = derivs + (size_t)p * N_DESC + l16 * 4;
    const size_t ds = (size_t)N_PAIRS * N_DESC;
    float4 v0 = __ldcs((const float4*)(base));
    float4 v1 = __ldcs((const float4*)(base + ds));
    float4 v2 = __ldcs((const float4*)(base + 2 * ds));

    float s0 = fmaf(v0.x, g.x, fmaf(v0.y, g.y, fmaf(v0.z, g.z, v0.w * g.w)));
    float s1 = fmaf(v1.x, g.x, fmaf(v1.y, g.y, fmaf(v1.z, g.z, v1.w * g.w)));
    float s2 = fmaf(v2.x, g.x, fmaf(v2.y, g.y, fmaf(v2.z, g.z, v2.w * g.w)));

    // reduce within each 16-lane half (xor offsets stay inside the half)
    #pragma unroll
    for (int o = 8; o > 0; o >>= 1) {
        s0 += __shfl_xor_sync(0xFFFFFFFFu, s0, o);
        s1 += __shfl_xor_sync(0xFFFFFFFFu, s1, o);
        s2 += __shfl_xor_sync(0xFFFFFFFFu, s2, o);
    }

    if (l16 < 3) {
        float s = (l16 == 0) ? s0 : (l16 == 1) ? s1 : s2;
        atomicAdd(out_f + (size_t)l16 * N_ATOMS + nb, -s);
    }
}

// ---------------------------------------------------------------------------
extern "C" void kernel_launch(void* const* d_in, const int* in_sizes, int n_in,
                              void* d_out, int out_size) {
    const float* coeffs   = (const float*)d_in[0];   // [1, N_ATOMS, 64]
    const float* derivs   = (const float*)d_in[1];   // [1, 3, N_PAIRS, 64]
    const float* w1       = (const float*)d_in[2];
    const float* b1       = (const float*)d_in[3];
    const float* w_last   = (const float*)d_in[4];
    const float* b_last   = (const float*)d_in[5];
    const int*   central  = (const int*)d_in[6];
    const int*   neigh    = (const int*)d_in[7];
    float* out = (float*)d_out;                      // [0]=energy, [1..30000]=forces [3,N_ATOMS]

    // 1) g table + energy partials + force zeroing (single launch)
    table_energy_kernel<<<TABLE_BLOCKS, TABLE_TPB>>>(
        (const float4*)coeffs, (const float4*)w1, (const float4*)b1,
        (const float4*)w_last, out + 1);

    // 2) pair contraction + scatter + energy finalize (non-persistent)
    {
        int warps = N_PAIRS / 2;                 // 250000, exact
        int blocks = warps / 8;                  // 31250, exact (8 warps/block)
        pair_kernel<<<blocks, 256>>>(derivs, central, neigh, b_last, out);
    }
}

// round 14
// speedup vs baseline: 1.0053x; 1.0053x over previous
#include <cuda_runtime.h>

#define N_ATOMS 10000
#define N_PAIRS 500000
#define N_DESC  64

#define TABLE_TPB 256
#define TABLE_BLOCKS ((N_ATOMS * N_DESC / 4 + TABLE_TPB - 1) / TABLE_TPB)   // 625

// Precomputed per-atom table: g[n,d] = (1 - tanh^2(coeffs*w1+b1)) * w1[d] * w_last[d]
__device__ float g_table[N_ATOMS * N_DESC];
// Per-block energy partials from the table kernel
__device__ float e_partials[TABLE_BLOCKS];

// ---------------------------------------------------------------------------
// Kernel 1: build g table (float4-vectorized), zero forces, write per-block
// energy partials. One thread per 4 (atom,descriptor) elements.
// ---------------------------------------------------------------------------
__global__ void table_energy_kernel(const float4* __restrict__ coeffs4,
                                    const float4* __restrict__ w1_4,
                                    const float4* __restrict__ b1_4,
                                    const float4* __restrict__ wl_4,
                                    float* __restrict__ out_f) {   // out+1
    int idx = blockIdx.x * blockDim.x + threadIdx.x;   // over 160000 float4s
    float e_contrib = 0.0f;
    if (idx < N_ATOMS * N_DESC / 4) {
        int d4 = idx & (N_DESC / 4 - 1);               // descriptor group 0..15
        float4 w  = w1_4[d4];
        float4 b  = b1_4[d4];
        float4 wl = wl_4[d4];
        float4 c  = coeffs4[idx];
        float ex = tanhf(fmaf(c.x, w.x, b.x));
        float ey = tanhf(fmaf(c.y, w.y, b.y));
        float ez = tanhf(fmaf(c.z, w.z, b.z));
        float ew = tanhf(fmaf(c.w, w.w, b.w));
        float4 g;
        g.x = (1.0f - ex * ex) * w.x * wl.x;
        g.y = (1.0f - ey * ey) * w.y * wl.y;
        g.z = (1.0f - ez * ez) * w.z * wl.z;
        g.w = (1.0f - ew * ew) * w.w * wl.w;
        *(float4*)(g_table + idx * 4) = g;
        e_contrib = fmaf(ex, wl.x, fmaf(ey, wl.y, fmaf(ez, wl.z, ew * wl.w)));
    }
    // zero the force output (3*N_ATOMS = 30000 floats; out_f only 4B-aligned)
    if (idx < 3 * N_ATOMS) out_f[idx] = 0.0f;

    // block reduction of energy contribution
    __shared__ float red[TABLE_TPB / 32];
    #pragma unroll
    for (int o = 16; o > 0; o >>= 1)
        e_contrib += __shfl_xor_sync(0xFFFFFFFFu, e_contrib, o);
    int lane = threadIdx.x & 31;
    int wid = threadIdx.x >> 5;
    if (lane == 0) red[wid] = e_contrib;
    __syncthreads();
    if (wid == 0) {
        float v = (lane < (TABLE_TPB >> 5)) ? red[lane] : 0.0f;
        #pragma unroll
        for (int o = 16; o > 0; o >>= 1)
            v += __shfl_xor_sync(0xFFFFFFFFu, v, o);
        if (lane == 0) e_partials[blockIdx.x] = v;
    }
}

// ---------------------------------------------------------------------------
// Kernel 2: pair contraction + scatter. Non-persistent (wall-clock best):
// TWO pairs per warp, lanes 0-15 -> pair 2w, lanes 16-31 -> pair 2w+1.
// Each lane owns 4 descriptors (float4); each deriv load is one warp-wide
// contiguous 512 B LDG.128. Derivs use __ldcs (evict-first) so L2 keeps
// g_table + the force accumulator resident.
// Block 0 / warp 0 additionally finalizes the energy from the partials.
// Grid covers exactly N_PAIRS/2 warps — no bounds check needed.
// ---------------------------------------------------------------------------
__global__ void __launch_bounds__(256) pair_kernel(
    const float* __restrict__ derivs,          // [3, N_PAIRS, 64]
    const int* __restrict__ central,
    const int* __restrict__ neigh,
    const float* __restrict__ b_last,
    float* __restrict__ out)                   // [0]=energy, [1..]=forces [3,N_ATOMS]
{
    const unsigned lane = threadIdx.x & 31;
    float* out_f = out + 1;

    // ---- energy finalize (one warp; table kernel already completed) ----
    if (blockIdx.x == 0 && (threadIdx.x >> 5) == 0) {
        float v = 0.0f;
        for (int i = lane; i < TABLE_BLOCKS; i += 32) v += e_partials[i];
        #pragma unroll
        for (int o = 16; o > 0; o >>= 1)
            v += __shfl_xor_sync(0xFFFFFFFFu, v, o);
        if (lane == 0) out[0] = v * (1.0f / (float)N_ATOMS) + b_last[0];
    }

    unsigned gtid = blockIdx.x * 256 + threadIdx.x;
    unsigned warp = gtid >> 5;
    unsigned p = warp * 2 + (lane >> 4);       // pair served by this lane
    unsigned l16 = lane & 15;

    int c  = __ldg(central + p);
    int nb = __ldg(neigh + p);

    // gather g row (L2-resident), 4 descriptors per lane
    float4 g = *(const float4*)(g_table + (size_t)c * N_DESC + l16 * 4);

    const float* base = derivs + (size_t)p * N_DESC + l16 * 4;
    const size_t ds = (size_t)N_PAIRS * N_DESC;
    float4 v0 = __ldcs((const float4*)(base));
    float4 v1 = __ldcs((const float4*)(base + ds));
    float4 v2 = __ldcs((const float4*)(base + 2 * ds));

    float s0 = fmaf(v0.x, g.x, fmaf(v0.y, g.y, fmaf(v0.z, g.z, v0.w * g.w)));
    float s1 = fmaf(v1.x, g.x, fmaf(v1.y, g.y, fmaf(v1.z, g.z, v1.w * g.w)));
    float s2 = fmaf(v2.x, g.x, fmaf(v2.y, g.y, fmaf(v2.z, g.z, v2.w * g.w)));

    // reduce within each 16-lane half (xor offsets stay inside the half)
    #pragma unroll
    for (int o = 8; o > 0; o >>= 1) {
        s0 += __shfl_xor_sync(0xFFFFFFFFu, s0, o);
        s1 += __shfl_xor_sync(0xFFFFFFFFu, s1, o);
        s2 += __shfl_xor_sync(0xFFFFFFFFu, s2, o);
    }

    if (l16 < 3) {
        float s = (l16 == 0) ? s0 : (l16 == 1) ? s1 : s2;
        atomicAdd(out_f + (size_t)l16 * N_ATOMS + nb, -s);
    }
}

// ---------------------------------------------------------------------------
extern "C" void kernel_launch(void* const* d_in, const int* in_sizes, int n_in,
                              void* d_out, int out_size) {
    const float* coeffs   = (const float*)d_in[0];   // [1, N_ATOMS, 64]
    const float* derivs   = (const float*)d_in[1];   // [1, 3, N_PAIRS, 64]
    const float* w1       = (const float*)d_in[2];
    const float* b1       = (const float*)d_in[3];
    const float* w_last   = (const float*)d_in[4];
    const float* b_last   = (const float*)d_in[5];
    const int*   central  = (const int*)d_in[6];
    const int*   neigh    = (const int*)d_in[7];
    float* out = (float*)d_out;                      // [0]=energy, [1..30000]=forces [3,N_ATOMS]

    // 1) g table + energy partials + force zeroing (single launch)
    table_energy_kernel<<<TABLE_BLOCKS, TABLE_TPB>>>(
        (const float4*)coeffs, (const float4*)w1, (const float4*)b1,
        (const float4*)w_last, out + 1);

    // 2) pair contraction + scatter + energy finalize (non-persistent)
    {
        int warps = N_PAIRS / 2;                 // 250000, exact
        int blocks = warps / 8;                  // 31250, exact (8 warps/block)
        pair_kernel<<<blocks, 256>>>(derivs, central, neigh, b_last, out);
    }
}